// round 15
// baseline (speedup 1.0000x reference)
#include <cuda_runtime.h>
#include <stdint.h>

// KVCache update: out = concat(k_cache, v_cache) with rows at pos_ids replaced
// by new k/v. pos_ids int32[16] (int64-layout auto-detected).
// Output f32[2,8,8192,128] = 64 MiB. Traffic floor: 64MB read + 64MB write.
//
// FINAL (converged; best measured 18.94us = ~7.1TB/s mixed r/w = ~89% of
// 8TB/s DRAM spec — at the mixed-stream roofline):
//  - fused single pass, float4, fully coalesced
//  - evict_last loads + __stcs evict-first stores
//  - persistent ONE-WAVE grid (148 SMs x 4 CTAs): avoids wave-seam ramps in
//    graph-replay steady state
//  - MLP=8 per thread, chunk-uniform tensor/head selects hoisted
//  - shared s->row byte table replaces per-element position compares
// Bracketed dead-ends: MLP=4 (-), MLP=16 (cold +1.2us), 3 & 5 CTAs/SM (-),
// direct-mapped grid (+2.3us warm), wt stores (+4.4us), evict_last stores
// (+5us), CE memcpy+scatter (+11.9us).

constexpr int N_HEADS   = 8;
constexpr int CTX       = 8192;
constexpr int HEAD_DIM  = 128;
constexpr int N_NEW     = 16;
constexpr int D4        = HEAD_DIM / 4;              // 32 float4 per row
constexpr int PER_TENSOR_V4 = N_HEADS * CTX * D4;    // 2,097,152
constexpr int TOTAL_V4      = 2 * PER_TENSOR_V4;     // 4,194,304
constexpr int THREADS    = 256;
constexpr int PER_THREAD = 8;
constexpr int CHUNK_V4   = THREADS * PER_THREAD;     // 2048 float4 = 64 rows, 1 head
constexpr int N_CHUNKS   = TOTAL_V4 / CHUNK_V4;      // 2048 (1024 K + 1024 V)
constexpr int CHUNKS_PER_TENSOR = PER_TENSOR_V4 / CHUNK_V4;  // 1024
constexpr int CHUNKS_PER_HEAD   = CTX * D4 / CHUNK_V4;       // 128
constexpr int GRID       = 592;                      // 148 SMs * 4 CTAs: one wave

__device__ __forceinline__ float4 ld_persist(const float4* p, uint64_t pol) {
    float4 v;
    asm volatile("ld.global.L2::cache_hint.v4.f32 {%0,%1,%2,%3}, [%4], %5;"
                 : "=f"(v.x), "=f"(v.y), "=f"(v.z), "=f"(v.w)
                 : "l"(p), "l"(pol));
    return v;
}

__global__ void __launch_bounds__(THREADS, 4)
kvcache_update_kernel(const int* __restrict__ pos32,
                      const float4* __restrict__ knew,
                      const float4* __restrict__ vnew,
                      const float4* __restrict__ kcache,
                      const float4* __restrict__ vcache,
                      float4* __restrict__ out)
{
    __shared__ uint8_t tbl[CTX];   // s -> j+1, 0 = not updated

    // Zero the table: 8192 B = 512 uint4; 2 per thread.
    uint4* tbl4 = reinterpret_cast<uint4*>(tbl);
    tbl4[threadIdx.x]           = make_uint4(0, 0, 0, 0);
    tbl4[threadIdx.x + THREADS] = make_uint4(0, 0, 0, 0);
    __syncthreads();

    if (threadIdx.x == 0) {
        // int64-vs-int32 layout detection (values < 2^31 -> odd words all zero).
        bool is64 = true;
        #pragma unroll
        for (int i = 1; i < 16; i += 2)
            if (pos32[i] != 0) is64 = false;
        // Sequential fill: last duplicate wins (scatter semantics).
        #pragma unroll
        for (int i = 0; i < N_NEW; i++) {
            int s = is64 ? pos32[2 * i] : pos32[i];
            tbl[s] = (uint8_t)(i + 1);
        }
    }
    __syncthreads();

    // Persisting (evict_last) policy for the cache read stream only.
    uint64_t pol;
    asm("createpolicy.fractional.L2::evict_last.b64 %0, 1.0;" : "=l"(pol));

    for (int chunk = blockIdx.x; chunk < N_CHUNKS; chunk += GRID) {
        // Chunk-uniform tensor and head.
        const bool isV = chunk >= CHUNKS_PER_TENSOR;
        const int  tc  = isV ? chunk - CHUNKS_PER_TENSOR : chunk;  // within tensor
        const int  h   = tc / CHUNKS_PER_HEAD;
        const float4* __restrict__ cache = isV ? vcache : kcache;
        const float4* __restrict__ newkv = (isV ? vnew : knew) + h * N_NEW * D4;

        const int rbase = tc * CHUNK_V4 + threadIdx.x;   // index within tensor
        const int obase = chunk * CHUNK_V4 + threadIdx.x;

        float4 vals[PER_THREAD];
        #pragma unroll
        for (int c = 0; c < PER_THREAD; c++) {
            int r  = rbase + c * THREADS;
            int d4 = r & (D4 - 1);
            int s  = (r >> 5) & (CTX - 1);
            int j  = tbl[s];                              // broadcast LDS (row-uniform)
            const float4* src = j ? &newkv[(j - 1) * D4 + d4] : &cache[r];
            vals[c] = ld_persist(src, pol);
        }
        #pragma unroll
        for (int c = 0; c < PER_THREAD; c++)
            __stcs(&out[obase + c * THREADS], vals[c]);   // evict-first stream
    }
}

extern "C" void kernel_launch(void* const* d_in, const int* in_sizes, int n_in,
                              void* d_out, int out_size)
{
    const int*    pos    = (const int*)d_in[0];
    const float4* knew   = (const float4*)d_in[1];
    const float4* vnew   = (const float4*)d_in[2];
    const float4* kcache = (const float4*)d_in[3];
    const float4* vcache = (const float4*)d_in[4];
    float4*       out    = (float4*)d_out;

    kvcache_update_kernel<<<GRID, THREADS>>>(pos, knew, vnew, kcache, vcache, out);
}

// round 16
// speedup vs baseline: 1.0665x; 1.0665x over previous
#include <cuda_runtime.h>
#include <stdint.h>

// KVCache update: out = concat(k_cache, v_cache) with rows at pos_ids replaced
// by new k/v. pos_ids int32[16] (int64-layout auto-detected).
// Output f32[2,8,8192,128] = 64 MiB. Traffic floor: 64MB read + 64MB write.
//
// R16 probe: 512-thread CTAs, 2 CTAs/SM (same warps/SM and in-flight loads
// as the converged R7 config, but half the per-CTA table-build overhead and
// half the shared-table replicas). Everything else = R7: evict_last loads +
// __stcs stores, persistent one-wave grid, MLP=8, chunk-uniform tensor/head.

constexpr int N_HEADS   = 8;
constexpr int CTX       = 8192;
constexpr int HEAD_DIM  = 128;
constexpr int N_NEW     = 16;
constexpr int D4        = HEAD_DIM / 4;              // 32 float4 per row
constexpr int PER_TENSOR_V4 = N_HEADS * CTX * D4;    // 2,097,152
constexpr int TOTAL_V4      = 2 * PER_TENSOR_V4;     // 4,194,304
constexpr int THREADS    = 512;
constexpr int PER_THREAD = 8;
constexpr int CHUNK_V4   = THREADS * PER_THREAD;     // 4096 float4 = 128 rows, 1 head
constexpr int N_CHUNKS   = TOTAL_V4 / CHUNK_V4;      // 1024 (512 K + 512 V)
constexpr int CHUNKS_PER_TENSOR = PER_TENSOR_V4 / CHUNK_V4;  // 512
constexpr int CHUNKS_PER_HEAD   = CTX * D4 / CHUNK_V4;       // 64
constexpr int CTAS_PER_SM = 2;
constexpr int GRID       = 148 * CTAS_PER_SM;        // 296: one wave

__device__ __forceinline__ float4 ld_persist(const float4* p, uint64_t pol) {
    float4 v;
    asm volatile("ld.global.L2::cache_hint.v4.f32 {%0,%1,%2,%3}, [%4], %5;"
                 : "=f"(v.x), "=f"(v.y), "=f"(v.z), "=f"(v.w)
                 : "l"(p), "l"(pol));
    return v;
}

__global__ void __launch_bounds__(THREADS, CTAS_PER_SM)
kvcache_update_kernel(const int* __restrict__ pos32,
                      const float4* __restrict__ knew,
                      const float4* __restrict__ vnew,
                      const float4* __restrict__ kcache,
                      const float4* __restrict__ vcache,
                      float4* __restrict__ out)
{
    __shared__ uint8_t tbl[CTX];   // s -> j+1, 0 = not updated

    // Zero the table: 8192 B = 512 uint4; 1 per thread.
    reinterpret_cast<uint4*>(tbl)[threadIdx.x] = make_uint4(0, 0, 0, 0);
    __syncthreads();

    if (threadIdx.x == 0) {
        // int64-vs-int32 layout detection (values < 2^31 -> odd words all zero).
        bool is64 = true;
        #pragma unroll
        for (int i = 1; i < 16; i += 2)
            if (pos32[i] != 0) is64 = false;
        // Sequential fill: last duplicate wins (scatter semantics).
        #pragma unroll
        for (int i = 0; i < N_NEW; i++) {
            int s = is64 ? pos32[2 * i] : pos32[i];
            tbl[s] = (uint8_t)(i + 1);
        }
    }
    __syncthreads();

    // evict_last policy for the cache read stream.
    uint64_t pol;
    asm("createpolicy.fractional.L2::evict_last.b64 %0, 1.0;" : "=l"(pol));

    for (int chunk = blockIdx.x; chunk < N_CHUNKS; chunk += GRID) {
        // Chunk-uniform tensor and head.
        const bool isV = chunk >= CHUNKS_PER_TENSOR;
        const int  tc  = isV ? chunk - CHUNKS_PER_TENSOR : chunk;  // within tensor
        const int  h   = tc / CHUNKS_PER_HEAD;
        const float4* __restrict__ cache = isV ? vcache : kcache;
        const float4* __restrict__ newkv = (isV ? vnew : knew) + h * N_NEW * D4;

        const int rbase = tc * CHUNK_V4 + threadIdx.x;   // index within tensor
        const int obase = chunk * CHUNK_V4 + threadIdx.x;

        float4 vals[PER_THREAD];
        #pragma unroll
        for (int c = 0; c < PER_THREAD; c++) {
            int r  = rbase + c * THREADS;
            int d4 = r & (D4 - 1);
            int s  = (r >> 5) & (CTX - 1);
            int j  = tbl[s];                              // broadcast LDS (row-uniform)
            const float4* src = j ? &newkv[(j - 1) * D4 + d4] : &cache[r];
            vals[c] = ld_persist(src, pol);
        }
        #pragma unroll
        for (int c = 0; c < PER_THREAD; c++)
            __stcs(&out[obase + c * THREADS], vals[c]);   // evict-first stream
    }
}

extern "C" void kernel_launch(void* const* d_in, const int* in_sizes, int n_in,
                              void* d_out, int out_size)
{
    const int*    pos    = (const int*)d_in[0];
    const float4* knew   = (const float4*)d_in[1];
    const float4* vnew   = (const float4*)d_in[2];
    const float4* kcache = (const float4*)d_in[3];
    const float4* vcache = (const float4*)d_in[4];
    float4*       out    = (float4*)d_out;

    kvcache_update_kernel<<<GRID, THREADS>>>(pos, knew, vnew, kcache, vcache, out);
}